// round 14
// baseline (speedup 1.0000x reference)
#include <cuda_runtime.h>
#include <math.h>
#include <stdint.h>

#define EPSF 1e-8f
#define CR   416                          // rows cached in SMEM (of 512)
#define DYN_SMEM (CR * 128 * 4)           // 212992 B dynamic smem
#define NKS  16                           // fc k-splits

// Scratch: NKS k-split partials of the FC output (NKS x 512 x 134).
__device__ float g_fcp[NKS * 512 * 134];

__device__ __forceinline__ float softplus_f(float x) {
    return (x > 20.0f) ? x : log1pf(expf(x));
}

#define CPA16(dst_u32, src_ptr) \
    asm volatile("cp.async.cg.shared.global [%0], [%1], 16;" :: "r"(dst_u32), "l"(src_ptr))
#define CPA_COMMIT() asm volatile("cp.async.commit_group;")

// ---------------------------------------------------------------------------
// Kernel 1: FC partials. Grid (32 b-groups, 16 k-splits), block (136,4).
// 16 batch rows/CTA, K-chunk 64 (cz splits into 16). W L2 traffic ~17MB.
// 512 CTAs fill the chip.
// ---------------------------------------------------------------------------
__global__ __launch_bounds__(544) void fc_kernel(const float* __restrict__ co,
                                                 const float* __restrict__ W,
                                                 const float* __restrict__ bias) {
    __shared__ __align__(16) float s_co[16 * 64];    // 16 rows x 64 c-chunk
    __shared__ float s_p[4][16][136];                // partials [cz][row][j]
    const int b0 = blockIdx.x * 16;
    const int ks = blockIdx.y;                       // k-split 0..15
    const int j  = threadIdx.x;                      // 0..135 (active < 134)
    const int cz = threadIdx.y;                      // 0..3
    const int tid = threadIdx.x + threadIdx.y * 136;

    // stage co[b0..b0+15][ks*64 .. ks*64+64) -> s_co
    for (int i = tid; i < 1024; i += 544) {
        int r = i >> 6, c = i & 63;
        s_co[r * 64 + c] = co[(size_t)(b0 + r) * 1024 + ks * 64 + c];
    }
    __syncthreads();

    if (j < 134) {
        const float* wp = W + (size_t)(ks * 64) * 134 + j;
        const int c0 = cz * 16;
        float a[16];
#pragma unroll
        for (int r = 0; r < 16; ++r) a[r] = 0.f;
#pragma unroll
        for (int c = c0; c < c0 + 16; ++c) {
            float w = wp[c * 134];
#pragma unroll
            for (int r = 0; r < 16; ++r) a[r] += w * s_co[r * 64 + c];
        }
#pragma unroll
        for (int r = 0; r < 16; ++r) s_p[cz][r][j] = a[r];
    }
    __syncthreads();

    if (cz == 0 && j < 134) {
        float bj = (ks == 0) ? bias[j] : 0.0f;
#pragma unroll
        for (int r = 0; r < 16; ++r) {
            float v = s_p[0][r][j] + s_p[1][r][j] + s_p[2][r][j] + s_p[3][r][j] + bj;
            g_fcp[((size_t)ks * 512 + b0 + r) * 134 + j] = v;
        }
    }
}

// ---------------------------------------------------------------------------
// Block reduction helpers (512 threads = 16 warps).
// ---------------------------------------------------------------------------
__device__ __forceinline__ float block_sum(float v, float* s_red, int wid, int lane) {
#pragma unroll
    for (int o = 16; o; o >>= 1) v += __shfl_xor_sync(0xffffffffu, v, o);
    __syncthreads();
    if (lane == 0) s_red[wid] = v;
    __syncthreads();
    if (wid == 0) {
        float x = (lane < 16) ? s_red[lane] : 0.0f;
#pragma unroll
        for (int o = 8; o; o >>= 1) x += __shfl_xor_sync(0xffffffffu, x, o);
        if (lane == 0) s_red[16] = x;
    }
    __syncthreads();
    return s_red[16];
}

__device__ __forceinline__ float block_max(float v, float* s_red, int wid, int lane) {
#pragma unroll
    for (int o = 16; o; o >>= 1) v = fmaxf(v, __shfl_xor_sync(0xffffffffu, v, o));
    __syncthreads();
    if (lane == 0) s_red[wid] = v;
    __syncthreads();
    if (wid == 0) {
        float x = (lane < 16) ? s_red[lane] : -3.4e38f;
#pragma unroll
        for (int o = 8; o; o >>= 1) x = fmaxf(x, __shfl_xor_sync(0xffffffffu, x, o));
        if (lane == 0) s_red[16] = x;
    }
    __syncthreads();
    return s_red[16];
}

// ---------------------------------------------------------------------------
// Chunk consumer: wait until <=WAITN cp.async groups pending, then cosine
// logits for CNT rows of this warp's stride-16 row set, from the SMEM cache.
// Each lane reads exactly the float4 it copied itself -> no barrier needed.
// ---------------------------------------------------------------------------
template <int G, int CNT, int WAITN>
__device__ __forceinline__ void do_chunk(const float4* __restrict__ cache4,
                                         const float4 k4, float beta_ink,
                                         float* __restrict__ s_u,
                                         int wid, int lane) {
    asm volatile("cp.async.wait_group %0;" :: "n"(WAITN));
    float d[CNT], q[CNT];
#pragma unroll
    for (int i = 0; i < CNT; ++i) {
        const int n = wid + 16 * (4 * G + i);
        float4 v = cache4[n * 32 + lane];
        d[i] = v.x * k4.x + v.y * k4.y + v.z * k4.z + v.w * k4.w;
        q[i] = v.x * v.x + v.y * v.y + v.z * v.z + v.w * v.w;
    }
#pragma unroll
    for (int o = 16; o; o >>= 1) {
#pragma unroll
        for (int i = 0; i < CNT; ++i) {
            d[i] += __shfl_xor_sync(0xffffffffu, d[i], o);
            q[i] += __shfl_xor_sync(0xffffffffu, q[i], o);
        }
    }
    if (lane == 0) {
#pragma unroll
        for (int i = 0; i < CNT; ++i)
            s_u[wid + 16 * (4 * G + i)] = beta_ink * d[i] / (sqrtf(q[i]) + EPSF);
    }
}

// ---------------------------------------------------------------------------
// Kernel 2: fused NTM head. 1 CTA/row, 512 threads, 1 CTA/SM.
// Phase B: 6 keep-row LDGs issued FIRST (land first in the L1tex FIFO),
// then 26 cp.async/thread stream the other 416 rows straight to SMEM
// (212KB/SM in flight -> DRAM saturation), in 7 commit groups consumed with
// staged wait_group while later groups are still in flight.
// Phases C/D touch no global memory.
// Warp w owns rows n = w + 16k; k<26 cached in SMEM, k>=26 in keep[] regs.
// ---------------------------------------------------------------------------
__global__ __launch_bounds__(512, 1) void ntm_kernel(const float* __restrict__ mem,
                                                     const float* __restrict__ prev_w,
                                                     float* __restrict__ d_out) {
    extern __shared__ __align__(16) float s_cache[];     // CR*128 floats
    __shared__ __align__(16) float s_k[128];
    __shared__ float s_raw[8];
    __shared__ float s_scal[8];          // beta, g, s0,s1,s2, gamma, inv_norm_k
    __shared__ float s_w[512];
    __shared__ float s_red[32];
    __shared__ __align__(16) float s_u[2048];   // logits / wg / warp partials

    const int b    = blockIdx.x;
    const int tid  = threadIdx.x;
    const int wid  = tid >> 5;
    const int lane = tid & 31;

    // ---- Phase A: sum FC partials -> k + scalar gates ----
    if (tid < 134) {
        const float* p = g_fcp + (size_t)b * 134 + tid;
        float v = 0.f;
#pragma unroll
        for (int ks = 0; ks < NKS; ++ks) v += p[(size_t)ks * 512 * 134];
        if (tid < 128) s_k[tid] = v;
        else           s_raw[tid - 128] = v;
    }
    __syncthreads();

    if (tid == 0) {
        float beta = softplus_f(s_raw[0]);
        float g = 1.0f / (1.0f + expf(-s_raw[1]));
        float x0 = s_raw[2], x1 = s_raw[3], x2 = s_raw[4];
        float mx = fmaxf(x0, fmaxf(x1, x2));
        float e0 = expf(x0 - mx), e1 = expf(x1 - mx), e2 = expf(x2 - mx);
        float inv = 1.0f / (e0 + e1 + e2);
        s_scal[0] = beta; s_scal[1] = g;
        s_scal[2] = e0 * inv; s_scal[3] = e1 * inv; s_scal[4] = e2 * inv;
        s_scal[5] = 1.0f + softplus_f(s_raw[5]);
    }
    if (wid == 0) {
        float4 k4 = ((const float4*)s_k)[lane];
        float ss = k4.x * k4.x + k4.y * k4.y + k4.z * k4.z + k4.w * k4.w;
#pragma unroll
        for (int o = 16; o; o >>= 1) ss += __shfl_xor_sync(0xffffffffu, ss, o);
        if (lane == 0) s_scal[6] = 1.0f / (sqrtf(ss) + EPSF);
    }
    __syncthreads();

    const float beta_ink = s_scal[0] * s_scal[6];     // beta / ||k||
    const float4 k4 = ((const float4*)s_k)[lane];
    const float4* memb4 = (const float4*)(mem + (size_t)b * (512 * 128));
    float4* cache4 = (float4*)s_cache;
    float4 keep[6];                      // rows with k = 26..31 (regs)

    // ---- Phase B issue: keep LDGs first, then all cp.asyncs ----
#pragma unroll
    for (int i = 0; i < 6; ++i)
        keep[i] = memb4[(wid + 16 * (26 + i)) * 32 + lane];

    const unsigned int sbase = (unsigned int)__cvta_generic_to_shared(s_cache);
#pragma unroll
    for (int g = 0; g < 6; ++g) {
#pragma unroll
        for (int i = 0; i < 4; ++i) {
            const int idx = (wid + 16 * (4 * g + i)) * 32 + lane;
            CPA16(sbase + idx * 16, memb4 + idx);
        }
        CPA_COMMIT();
    }
#pragma unroll
    for (int i = 0; i < 2; ++i) {        // rows k = 24, 25
        const int idx = (wid + 16 * (24 + i)) * 32 + lane;
        CPA16(sbase + idx * 16, memb4 + idx);
    }
    CPA_COMMIT();                        // 7 groups total

    // ---- keep-row logits while cp.asyncs stream ----
    {
        float d[6], q[6];
#pragma unroll
        for (int i = 0; i < 6; ++i) {
            float4 v = keep[i];
            d[i] = v.x * k4.x + v.y * k4.y + v.z * k4.z + v.w * k4.w;
            q[i] = v.x * v.x + v.y * v.y + v.z * v.z + v.w * v.w;
        }
#pragma unroll
        for (int o = 16; o; o >>= 1) {
#pragma unroll
            for (int i = 0; i < 6; ++i) {
                d[i] += __shfl_xor_sync(0xffffffffu, d[i], o);
                q[i] += __shfl_xor_sync(0xffffffffu, q[i], o);
            }
        }
        if (lane == 0) {
#pragma unroll
            for (int i = 0; i < 6; ++i)
                s_u[wid + 16 * (26 + i)] = beta_ink * d[i] / (sqrtf(q[i]) + EPSF);
        }
    }

    // ---- staged SMEM chunk consumption (overlaps in-flight groups) ----
    do_chunk<0, 4, 6>(cache4, k4, beta_ink, s_u, wid, lane);
    do_chunk<1, 4, 5>(cache4, k4, beta_ink, s_u, wid, lane);
    do_chunk<2, 4, 4>(cache4, k4, beta_ink, s_u, wid, lane);
    do_chunk<3, 4, 3>(cache4, k4, beta_ink, s_u, wid, lane);
    do_chunk<4, 4, 2>(cache4, k4, beta_ink, s_u, wid, lane);
    do_chunk<5, 4, 1>(cache4, k4, beta_ink, s_u, wid, lane);
    do_chunk<6, 2, 0>(cache4, k4, beta_ink, s_u, wid, lane);
    __syncthreads();

    // ---- Phase C: softmax over N, gate, shift, sharpen ----
    float logit = s_u[tid];
    float vmax = block_max(logit, s_red, wid, lane);
    float e = expf(logit - vmax);
    float esum = block_sum(e, s_red, wid, lane);
    float w_c = e / esum;

    float g = s_scal[1];
    float wg = g * w_c + (1.0f - g) * prev_w[b * 512 + tid];
    s_u[512 + tid] = wg;
    __syncthreads();

    float ws = s_scal[2] * s_u[512 + ((tid + 511) & 511)]
             + s_scal[3] * wg
             + s_scal[4] * s_u[512 + ((tid + 1) & 511)];
    float wp = expf(s_scal[5] * logf(ws));          // ws > 0 always
    float psum = block_sum(wp, s_red, wid, lane);   // internal syncs order s_u reads
    float w = wp / (psum + EPSF);
    s_w[tid] = w;
    d_out[512 * 128 + b * 512 + tid] = w;           // output w (second element)
    __syncthreads();                                // s_w ready; s_u free

    // ---- Phase D: read_vec from SMEM cache + keep regs only ----
    float4 acc = make_float4(0.f, 0.f, 0.f, 0.f);
#pragma unroll
    for (int k = 0; k < 26; ++k) {
        const int n = wid + 16 * k;
        float4 v = cache4[n * 32 + lane];
        float wn = s_w[n];
        acc.x += wn * v.x; acc.y += wn * v.y;
        acc.z += wn * v.z; acc.w += wn * v.w;
    }
#pragma unroll
    for (int k = 26; k < 32; ++k) {
        float wn = s_w[wid + 16 * k];
        acc.x += wn * keep[k - 26].x; acc.y += wn * keep[k - 26].y;
        acc.z += wn * keep[k - 26].z; acc.w += wn * keep[k - 26].w;
    }
    ((float4*)s_u)[wid * 32 + lane] = acc;          // 16 warps x 128 floats
    __syncthreads();

    if (tid < 128) {
        float r = 0.f;
#pragma unroll
        for (int i = 0; i < 16; ++i) r += s_u[i * 128 + tid];
        d_out[b * 128 + tid] = r;                   // output read_vec
    }
}

// ---------------------------------------------------------------------------
// Launch.
// ---------------------------------------------------------------------------
extern "C" void kernel_launch(void* const* d_in, const int* in_sizes, int n_in,
                              void* d_out, int out_size) {
    const float* co    = (const float*)d_in[0];   // (512, 1024)
    const float* prevw = (const float*)d_in[1];   // (512, 512)
    const float* mem   = (const float*)d_in[2];   // (512, 512, 128)
    const float* W     = (const float*)d_in[3];   // (1024, 134)
    const float* bias  = (const float*)d_in[4];   // (134,)

    cudaFuncSetAttribute(ntm_kernel, cudaFuncAttributeMaxDynamicSharedMemorySize,
                         DYN_SMEM);

    fc_kernel<<<dim3(32, 16), dim3(136, 4)>>>(co, W, bias);
    ntm_kernel<<<512, 512, DYN_SMEM>>>(mem, prevw, (float*)d_out);
}